// round 14
// baseline (speedup 1.0000x reference)
#include <cuda_runtime.h>
#include <math.h>
#include <stdint.h>

#define NN 100000
#define EE 800000
#define HH 128
#define G4 512
#define TT 200
#define BB 32
#define INQ 64
#define MAXT 1024
#define MAXSLOTS (MAXT + 8)
#define MAXL1 131072

// ---------------- device scratch (no allocs allowed) ----------------
__device__ float g_deg[NN];
__device__ int   g_flag[NN];
__device__ int   g_cnt[4];          // 0=slotCount 1=tgtEdgeCount 2=l1EdgeCount
__device__ int   g_tgt_src[MAXT];
__device__ int   g_tgt_t[MAXT];
__device__ int   g_tgt_slot[MAXT];
__device__ int   g_nodeOfSlot[MAXSLOTS];
__device__ int   g_l1_src[MAXL1];
__device__ int   g_l1_slot[MAXL1];
__device__ float g_xagg[MAXSLOTS * HH];  // layer-1 aggregated raw features
__device__ float g_h1[MAXSLOTS * HH];    // layer-1 output per slot
__device__ float g_hagg[8 * HH];         // layer-2 aggregated h1 at targets
__device__ float g_dvec[9 * HH];
__device__ float g_fw[9 * HH];
__device__ float g_xpre[TT * BB * G4];   // LSTM1 input gates (x-part + biases)
__device__ float g_h1out[BB * HH];       // LSTM1 final hidden
__device__ float g_xpre2[BB * G4];       // LSTM2 input gates

// HW tanh (sm_75+): 1 MUFU op; sigmoid via tanh identity
__device__ __forceinline__ float ftanh(float x) {
    float r; asm("tanh.approx.f32 %0, %1;" : "=f"(r) : "f"(x)); return r;
}
__device__ __forceinline__ float fsig(float x) {
    return fmaf(ftanh(0.5f * x), 0.5f, 0.5f);
}

// ---------------- zero scratch ----------------
__global__ void k_zero() {
    int i = blockIdx.x * 256 + threadIdx.x;
    if (i < NN) { g_deg[i] = 0.f; g_flag[i] = 0; }
    if (i < MAXSLOTS * HH) g_xagg[i] = 0.f;
    if (i < 8 * HH) g_hagg[i] = 0.f;
    if (i < 4) g_cnt[i] = 0;
}

// ---------------- edge pass 1: degree histogram + edges into targets ----------------
__global__ void k_scan1(const int* __restrict__ ei) {
    int e = blockIdx.x * 256 + threadIdx.x;
    if (e >= EE) return;
    int d = ei[EE + e];
    atomicAdd(&g_deg[d], 1.0f);
    if (d <= 7000 && (d % 1000) == 0) {   // TARGET = {0,1000,...,7000}
        int ti = d / 1000;
        int p = atomicAdd(&g_cnt[1], 1);
        if (p < MAXT) { g_tgt_src[p] = ei[e]; g_tgt_t[p] = ti; }
    }
}

// ---------------- dedupe target-edge sources into slots; slots 0..7 = targets ----------------
__global__ void k_dedupe() {
    __shared__ int s_src[MAXT];
    __shared__ int s_first[MAXT];
    __shared__ int s_slot[MAXT];
    int i = threadIdx.x;
    int nT = g_cnt[1]; if (nT > MAXT) nT = MAXT;
    if (i < 8) { g_flag[i * 1000] = i + 1; g_nodeOfSlot[i] = i * 1000; }
    int s = (i < nT) ? g_tgt_src[i] : -1;
    s_src[i] = s;
    __syncthreads();
    int slot = -1, first = 0;
    if (i < nT) {
        #pragma unroll
        for (int k = 0; k < 8; k++) if (s == k * 1000) slot = k;
        if (slot < 0) {
            first = 1;
            for (int j = 0; j < i; j++) if (s_src[j] == s) { first = 0; break; }
        }
    }
    s_first[i] = (i < nT && slot < 0) ? first : 0;
    s_slot[i] = slot;
    __syncthreads();
    if (i < nT && slot < 0) {
        if (first) {
            int rank = 0;
            for (int j = 0; j < i; j++) rank += s_first[j];
            s_slot[i] = 8 + rank;
        } else {
            int j = 0; while (s_src[j] != s) j++;
            int rj = 0;
            for (int q = 0; q < j; q++) rj += s_first[q];
            s_slot[i] = 8 + rj;
        }
    }
    __syncthreads();
    if (i < nT) {
        g_tgt_slot[i] = s_slot[i];
        if (s_first[i]) { g_nodeOfSlot[s_slot[i]] = s_src[i]; g_flag[s_src[i]] = s_slot[i] + 1; }
    }
    if (i == 0) {
        int tot = 0;
        for (int j = 0; j < nT; j++) tot += s_first[j];
        g_cnt[0] = 8 + tot;
    }
}

// ---------------- edge pass 2: edges whose dst is in the 1-hop set ----------------
__global__ void k_scan2(const int* __restrict__ ei) {
    int e = blockIdx.x * 256 + threadIdx.x;
    if (e >= EE) return;
    int d = ei[EE + e];
    int f = g_flag[d];
    if (f > 0) {
        int p = atomicAdd(&g_cnt[2], 1);
        if (p < MAXL1) { g_l1_src[p] = ei[e]; g_l1_slot[p] = f - 1; }
    }
}

// ---------------- GCN layer 1: aggregate RAW features per slot (linearity fold) ----------------
__global__ void k_l1agg(const float* __restrict__ x) {
    int cnt = g_cnt[2]; if (cnt > MAXL1) cnt = MAXL1;
    for (int idx = blockIdx.x; idx < cnt; idx += gridDim.x) {
        int src = g_l1_src[idx], slot = g_l1_slot[idx];
        int dn = g_nodeOfSlot[slot];
        float norm = rsqrtf(g_deg[src] + 1.f) * rsqrtf(g_deg[dn] + 1.f);
        atomicAdd(&g_xagg[slot * HH + threadIdx.x], x[src * HH + threadIdx.x] * norm);
    }
}

// ---------------- GCN layer 1: (agg + self) @ W1 + b1, relu -> g_h1 ----------------
__global__ void k_l1mat(const float* __restrict__ x, const float* __restrict__ W1,
                        const float* __restrict__ b1) {
    __shared__ float xs[HH];
    int nslots = g_cnt[0];
    for (int slot = blockIdx.x; slot < nslots; slot += gridDim.x) {
        int node = g_nodeOfSlot[slot];
        float rs = rsqrtf(g_deg[node] + 1.f);
        float di2 = rs * rs;
        __syncthreads();
        xs[threadIdx.x] = g_xagg[slot * HH + threadIdx.x] + x[node * HH + threadIdx.x] * di2;
        __syncthreads();
        float acc = 0.f;
        #pragma unroll 8
        for (int k = 0; k < HH; k++) acc += xs[k] * W1[k * HH + threadIdx.x];
        g_h1[slot * HH + threadIdx.x] = fmaxf(acc + b1[threadIdx.x], 0.f);
    }
}

// ---------------- GCN layer 2: aggregate h1 at the 8 targets (linearity fold) ----------------
__global__ void k_l2agg() {
    int cnt = g_cnt[1]; if (cnt > MAXT) cnt = MAXT;
    for (int i = blockIdx.x; i < cnt; i += gridDim.x) {
        int t = g_tgt_t[i], s = g_tgt_src[i], slot = g_tgt_slot[i];
        int tn = t * 1000;
        float norm = rsqrtf(g_deg[s] + 1.f) * rsqrtf(g_deg[tn] + 1.f);
        atomicAdd(&g_hagg[t * HH + threadIdx.x], g_h1[slot * HH + threadIdx.x] * norm);
    }
}

// ---------------- GCN layer 2: (agg + self) @ W2 + b2, relu -> g_dvec[0:1024] ----------------
__global__ void k_l2mat(const float* __restrict__ W2, const float* __restrict__ b2) {
    __shared__ float hs[HH];
    int t = blockIdx.x, o = threadIdx.x;
    int tn = t * 1000;
    float rs = rsqrtf(g_deg[tn] + 1.f);
    float di2 = rs * rs;
    hs[o] = g_hagg[t * HH + o] + g_h1[t * HH + o] * di2;   // slot t == target t
    __syncthreads();
    float acc = 0.f;
    #pragma unroll 8
    for (int k = 0; k < HH; k++) acc += hs[k] * W2[k * HH + o];
    g_dvec[t * HH + o] = fmaxf(acc + b2[o], 0.f);
}

// ---------------- LSTM1 input GEMM: xpre[t*32+b, n] = data0[b,t,:] @ Wih1[n,:] + bih1+bhh1 ----------------
__global__ __launch_bounds__(256) void k_xpre(const float* __restrict__ data0,
                                              const float* __restrict__ Wih1,
                                              const float* __restrict__ bih1,
                                              const float* __restrict__ bhh1) {
    __shared__ float xs[64][65];
    __shared__ float ws[64][65];   // ws[k][j]
    int rowbase = blockIdx.x * 64;
    int colbase = blockIdx.y * 64;
    int tid = threadIdx.x;
    for (int idx = tid; idx < 64 * 64; idx += 256) {
        int i = idx >> 6, k = idx & 63;
        int r = rowbase + i, b = r & 31, t = r >> 5;
        xs[i][k] = data0[(b * TT + t) * INQ + k];
    }
    for (int idx = tid; idx < 64 * 64; idx += 256) {
        int j = idx >> 6, k = idx & 63;
        ws[k][j] = Wih1[(colbase + j) * INQ + k];
    }
    __syncthreads();
    int tx = tid & 15, ty = tid >> 4;
    float acc[4][4] = {};
    #pragma unroll 8
    for (int k = 0; k < 64; k++) {
        float a[4], bb[4];
        #pragma unroll
        for (int u = 0; u < 4; u++) a[u] = xs[ty * 4 + u][k];
        #pragma unroll
        for (int v = 0; v < 4; v++) bb[v] = ws[k][tx * 4 + v];
        #pragma unroll
        for (int u = 0; u < 4; u++)
            #pragma unroll
            for (int v = 0; v < 4; v++) acc[u][v] = fmaf(a[u], bb[v], acc[u][v]);
    }
    #pragma unroll
    for (int u = 0; u < 4; u++) {
        int r = rowbase + ty * 4 + u;
        #pragma unroll
        for (int v = 0; v < 4; v++) {
            int n = colbase + tx * 4 + v;
            g_xpre[r * G4 + n] = acc[u][v] + bih1[n] + bhh1[n];
        }
    }
}

// ---------------- LSTM recurrence: 2-CTA cluster; TWO interleaved batches per cluster ----------
// Thread tid: gate gt = tid&3, h-offset m = tid>>2; hidx = rank*64+m. Weights shared across
// the 2 batches (no extra weight regs). Per step: phase1(A,B) over own halves; one wait
// (peer sends both halves then ONE release-arrive); phase2(A,B); activations; sends.
// Batch B's chain fills batch A's latency bubbles (issue was 17% — bubble-dominated).
#define MBAR_WAIT_CL(addr, parity) do {                                            \
    asm volatile("{\n\t.reg .pred P;\n\t"                                          \
        "WL_%=:\n\t"                                                               \
        "mbarrier.try_wait.parity.acquire.cluster.shared::cta.b64 P, [%0], %1, 0x989680;\n\t"\
        "@P bra.uni WD_%=;\n\t"                                                    \
        "bra.uni WL_%=;\n\t"                                                       \
        "WD_%=:\n\t}"                                                              \
        :: "r"(addr), "r"(parity) : "memory");                                     \
} while (0)

__global__ __launch_bounds__(256, 1) __cluster_dims__(2, 1, 1)
void k_lstm_cl(const float* __restrict__ Whh, int steps, int which, int nb) {
    __shared__ __align__(16) float sh_h[2][2][HH];   // [buf][batch][idx]
    __shared__ __align__(8) unsigned long long smb[2];
    int tid = threadIdx.x;
    int rank = (int)(blockIdx.x & 1);
    int b0 = (int)(blockIdx.x >> 1) * 2;   // first batch of this cluster (which==1)
    int gt = tid & 3;             // gate type 0..3 (i,f,g,o)
    int m  = tid >> 2;            // h-offset within my chunk (0..63)
    int hidx = (rank << 6) + m;   // global h index
    int row  = gt * HH + hidx;    // gate row this thread computes

    // one-time: weight row into registers, split own/peer halves with STATIC reg indices
    unsigned long long wqA[32], wqB[32];
    {
        const float4* w4own = (const float4*)(Whh + row * HH + (rank << 6));
        const float4* w4rem = (const float4*)(Whh + row * HH + ((1 ^ rank) << 6));
        #pragma unroll
        for (int q = 0; q < 16; q++) {
            float4 w = __ldg(&w4own[q]);
            asm("mov.b64 %0, {%1,%2};" : "=l"(wqA[2 * q])     : "f"(w.x), "f"(w.y));
            asm("mov.b64 %0, {%1,%2};" : "=l"(wqA[2 * q + 1]) : "f"(w.z), "f"(w.w));
        }
        #pragma unroll
        for (int q = 0; q < 16; q++) {
            float4 w = __ldg(&w4rem[q]);
            asm("mov.b64 %0, {%1,%2};" : "=l"(wqB[2 * q])     : "f"(w.x), "f"(w.y));
            asm("mov.b64 %0, {%1,%2};" : "=l"(wqB[2 * q + 1]) : "f"(w.z), "f"(w.w));
        }
    }

    if (tid < HH) { sh_h[0][0][tid] = 0.f; sh_h[0][1][tid] = 0.f; }
    if (tid == 0) {
        uint32_t bb0 = (uint32_t)__cvta_generic_to_shared(&smb[0]);
        uint32_t bb1 = (uint32_t)__cvta_generic_to_shared(&smb[1]);
        asm volatile("mbarrier.init.shared.b64 [%0], %1;" :: "r"(bb0), "r"(64u));
        asm volatile("mbarrier.init.shared.b64 [%0], %1;" :: "r"(bb1), "r"(64u));
    }

    uint32_t sh_base = (uint32_t)__cvta_generic_to_shared(&sh_h[0][0][0]);
    uint32_t lb0 = (uint32_t)__cvta_generic_to_shared(&smb[0]);
    uint32_t lb1 = (uint32_t)__cvta_generic_to_shared(&smb[1]);
    uint32_t peer = 1u ^ (uint32_t)rank;
    uint32_t rsh, rb0, rb1;
    asm("mapa.shared::cluster.u32 %0, %1, %2;" : "=r"(rsh) : "r"(sh_base), "r"(peer));
    asm("mapa.shared::cluster.u32 %0, %1, %2;" : "=r"(rb0) : "r"(lb0), "r"(peer));
    asm("mapa.shared::cluster.u32 %0, %1, %2;" : "=r"(rb1) : "r"(lb1), "r"(peer));
    __syncthreads();
    asm volatile("barrier.cluster.arrive.aligned;" ::: "memory");
    asm volatile("barrier.cluster.wait.aligned;" ::: "memory");

    int ph0 = 0, ph1 = 0;
    float cA = 0.f, cB = 0.f;
    int qbase = (tid & 31) & ~3;                   // quad base lane within warp
    uint32_t own_off = (uint32_t)(rank << 8);      // own half byte offset within a batch slab
    uint32_t rem_off = own_off ^ 256u;             // peer half byte offset
    uint32_t hx4 = (uint32_t)(hidx * 4);
    float accnA, accnB;
    if (which == 1) { accnA = g_xpre[b0 * G4 + row]; accnB = g_xpre[(b0 + 1) * G4 + row]; }
    else            { accnA = g_xpre2[row];          accnB = 0.f; }
    for (int s = 0; s < steps; s++) {
        int buf = s & 1;
        float accA = accnA, accB = accnB;
        if (s + 1 < steps) {
            if (which == 1) {
                accnA = g_xpre[((s + 1) * BB + b0) * G4 + row];
                accnB = g_xpre[((s + 1) * BB + b0 + 1) * G4 + row];
            } else {
                accnA = g_xpre2[(s + 1) * G4 + row];
            }
        }

        uint32_t slab = sh_base + ((uint32_t)buf << 10);   // [buf] slab: 2 batches * 512B
        unsigned long long aA0 = 0ull, aA1 = 0ull, aB0 = 0ull, aB1 = 0ull;

        // phase 1: OWN halves, batch A then B (independent chains, fills bubbles)
        #pragma unroll
        for (int q = 0; q < 16; q++) {
            unsigned long long hA01, hA23, hB01, hB23;
            asm volatile("ld.shared.v2.u64 {%0,%1}, [%2];"
                         : "=l"(hA01), "=l"(hA23) : "r"(slab + own_off + q * 16));
            asm volatile("ld.shared.v2.u64 {%0,%1}, [%2];"
                         : "=l"(hB01), "=l"(hB23) : "r"(slab + 512 + own_off + q * 16));
            asm("fma.rn.f32x2 %0, %1, %2, %0;" : "+l"(aA0) : "l"(wqA[2 * q]),     "l"(hA01));
            asm("fma.rn.f32x2 %0, %1, %2, %0;" : "+l"(aA1) : "l"(wqA[2 * q + 1]), "l"(hA23));
            asm("fma.rn.f32x2 %0, %1, %2, %0;" : "+l"(aB0) : "l"(wqA[2 * q]),     "l"(hB01));
            asm("fma.rn.f32x2 %0, %1, %2, %0;" : "+l"(aB1) : "l"(wqA[2 * q + 1]), "l"(hB23));
        }

        // wait for peer halves (both batches; hidden behind phase 1)
        if (s > 0) {
            if (buf) { MBAR_WAIT_CL(lb1, ph1); ph1 ^= 1; }
            else     { MBAR_WAIT_CL(lb0, ph0); ph0 ^= 1; }
        }

        // phase 2: PEER halves, batch A then B
        #pragma unroll
        for (int q = 0; q < 16; q++) {
            unsigned long long hA01, hA23, hB01, hB23;
            asm volatile("ld.shared.v2.u64 {%0,%1}, [%2];"
                         : "=l"(hA01), "=l"(hA23) : "r"(slab + rem_off + q * 16));
            asm volatile("ld.shared.v2.u64 {%0,%1}, [%2];"
                         : "=l"(hB01), "=l"(hB23) : "r"(slab + 512 + rem_off + q * 16));
            asm("fma.rn.f32x2 %0, %1, %2, %0;" : "+l"(aA0) : "l"(wqB[2 * q]),     "l"(hA01));
            asm("fma.rn.f32x2 %0, %1, %2, %0;" : "+l"(aA1) : "l"(wqB[2 * q + 1]), "l"(hA23));
            asm("fma.rn.f32x2 %0, %1, %2, %0;" : "+l"(aB0) : "l"(wqB[2 * q]),     "l"(hB01));
            asm("fma.rn.f32x2 %0, %1, %2, %0;" : "+l"(aB1) : "l"(wqB[2 * q + 1]), "l"(hB23));
        }

        float vA, vB;
        {
            float x0, y0, x1, y1;
            asm("add.rn.f32x2 %0, %0, %1;" : "+l"(aA0) : "l"(aA1));
            asm("mov.b64 {%0,%1}, %2;" : "=f"(x0), "=f"(y0) : "l"(aA0));
            vA = accA + (x0 + y0);
            asm("add.rn.f32x2 %0, %0, %1;" : "+l"(aB0) : "l"(aB1));
            asm("mov.b64 {%0,%1}, %2;" : "=f"(x1), "=f"(y1) : "l"(aB0));
            vB = accB + (x1 + y1);
        }

        // transform own gate FIRST, then quad-gather transformed values (both batches)
        float tA = (gt == 2) ? ftanh(vA) : fsig(vA);
        float tB = (gt == 2) ? ftanh(vB) : fsig(vB);
        float tA0 = __shfl_sync(0xffffffffu, tA, qbase + 0);
        float tA1 = __shfl_sync(0xffffffffu, tA, qbase + 1);
        float tA2 = __shfl_sync(0xffffffffu, tA, qbase + 2);
        float tA3 = __shfl_sync(0xffffffffu, tA, qbase + 3);
        float tB0 = __shfl_sync(0xffffffffu, tB, qbase + 0);
        float tB1 = __shfl_sync(0xffffffffu, tB, qbase + 1);
        float tB2 = __shfl_sync(0xffffffffu, tB, qbase + 2);
        float tB3 = __shfl_sync(0xffffffffu, tB, qbase + 3);

        cA = tA1 * cA + tA0 * tA2;
        float hA = tA3 * ftanh(cA);
        cB = tB1 * cB + tB0 * tB2;
        float hB = tB3 * ftanh(cB);

        if (s + 1 < steps) {
            int bn = (s + 1) & 1;
            uint32_t nslab_off = ((uint32_t)bn << 10);
            if (gt == 0) {
                sh_h[bn][0][hidx] = hA;
                sh_h[bn][1][hidx] = hB;
                uint32_t rgA = rsh + nslab_off + hx4;
                uint32_t rgB = rgA + 512u;
                uint32_t rb = bn ? rb1 : rb0;
                asm volatile("st.shared::cluster.f32 [%0], %1;" :: "r"(rgA), "f"(hA) : "memory");
                asm volatile("st.shared::cluster.f32 [%0], %1;" :: "r"(rgB), "f"(hB) : "memory");
                asm volatile("mbarrier.arrive.release.cluster.shared::cluster.b64 _, [%0];"
                             :: "r"(rb) : "memory");
            }
            __syncthreads();   // local sh_h[bn] visible to all warps' next phase-1
        } else {
            if (gt == 0) {
                if (which == 1) {
                    g_h1out[b0 * HH + hidx] = hA;
                    g_h1out[(b0 + 1) * HH + hidx] = hB;
                } else {
                    g_dvec[8 * HH + hidx] = hA;
                }
            }
        }
    }
}

// ---------------- LSTM2 input GEMM: xpre2[s, n] = h1out[s,:] @ Wih2[n,:] + biases ----------------
__global__ __launch_bounds__(128) void k_xpre2(const float* __restrict__ Wih2,
                                               const float* __restrict__ bih2,
                                               const float* __restrict__ bhh2) {
    __shared__ float hh[BB * HH];
    int tid = threadIdx.x;
    for (int idx = tid; idx < BB * HH; idx += 128) hh[idx] = g_h1out[idx];
    __syncthreads();
    int n = blockIdx.x * 128 + tid;
    float4 wreg[32];
    const float4* w4 = (const float4*)(Wih2 + n * HH);
    #pragma unroll
    for (int kk = 0; kk < 32; kk++) wreg[kk] = __ldg(&w4[kk]);
    float bias = bih2[n] + bhh2[n];
    for (int s = 0; s < BB; s++) {
        const float4* h4 = (const float4*)(hh + s * HH);
        float a0 = 0.f, a1 = 0.f, a2 = 0.f, a3 = 0.f;
        #pragma unroll
        for (int kk = 0; kk < 32; kk++) {
            float4 h = h4[kk];
            a0 = fmaf(wreg[kk].x, h.x, a0); a1 = fmaf(wreg[kk].y, h.y, a1);
            a2 = fmaf(wreg[kk].z, h.z, a2); a3 = fmaf(wreg[kk].w, h.w, a3);
        }
        g_xpre2[s * G4 + n] = bias + ((a0 + a1) + (a2 + a3));
    }
}

// ---------------- MLP head: fuse m1_w @ m2_w (no nonlinearity in head) ----------------
__global__ void k_fw(const float* __restrict__ m1w, const float* __restrict__ m2w) {
    int i = blockIdx.x;
    float s = 0.f;
    for (int j = threadIdx.x; j < 576; j += 64) s += m1w[i * 576 + j] * m2w[j];
    #pragma unroll
    for (int off = 16; off > 0; off >>= 1) s += __shfl_down_sync(0xffffffffu, s, off);
    __shared__ float sm[2];
    if ((threadIdx.x & 31) == 0) sm[threadIdx.x >> 5] = s;
    __syncthreads();
    if (threadIdx.x == 0) g_fw[i] = sm[0] + sm[1];
}

__global__ void k_final(const float* __restrict__ m1b, const float* __restrict__ m2w,
                        const float* __restrict__ m2b, float* __restrict__ out) {
    __shared__ float red[512];
    float s = 0.f;
    for (int i = threadIdx.x; i < 9 * HH; i += 512) s += g_dvec[i] * g_fw[i];
    for (int j = threadIdx.x; j < 576; j += 512) s += m1b[j] * m2w[j];
    red[threadIdx.x] = s;
    __syncthreads();
    for (int st = 256; st > 0; st >>= 1) {
        if (threadIdx.x < st) red[threadIdx.x] += red[threadIdx.x + st];
        __syncthreads();
    }
    if (threadIdx.x == 0) out[0] = red[0] + m2b[0];
}

// ---------------- launch ----------------
extern "C" void kernel_launch(void* const* d_in, const int* in_sizes, int n_in,
                              void* d_out, int out_size) {
    const float* data0 = (const float*)d_in[0];
    const float* data1 = (const float*)d_in[1];
    const int*   ei    = (const int*)d_in[2];
    const float* W1   = (const float*)d_in[3];
    const float* b1   = (const float*)d_in[4];
    const float* W2   = (const float*)d_in[5];
    const float* b2   = (const float*)d_in[6];
    const float* Wih1 = (const float*)d_in[7];
    const float* Whh1 = (const float*)d_in[8];
    const float* bih1 = (const float*)d_in[9];
    const float* bhh1 = (const float*)d_in[10];
    const float* Wih2 = (const float*)d_in[11];
    const float* Whh2 = (const float*)d_in[12];
    const float* bih2 = (const float*)d_in[13];
    const float* bhh2 = (const float*)d_in[14];
    const float* m1w  = (const float*)d_in[15];
    const float* m1b  = (const float*)d_in[16];
    const float* m2w  = (const float*)d_in[17];
    const float* m2b  = (const float*)d_in[18];
    float* out = (float*)d_out;

    static cudaStream_t s2 = nullptr;
    static cudaEvent_t evA = nullptr, evB = nullptr;
    if (!s2) {
        cudaStreamCreateWithFlags(&s2, cudaStreamNonBlocking);
        cudaEventCreateWithFlags(&evA, cudaEventDisableTiming);
        cudaEventCreateWithFlags(&evB, cudaEventDisableTiming);
    }

    // fork: GCN chain + head-weight fold run on s2, LSTM chain on default stream.
    // Host launch order puts k_lstm_cl 4th so ncu's fixed capture slot profiles it.
    cudaEventRecord(evA, 0);
    cudaStreamWaitEvent(s2, evA, 0);

    k_xpre<<<dim3(100, 8), 256>>>(data0, Wih1, bih1, bhh1);          // launch 1 (default)
    k_zero<<<(MAXSLOTS * HH + 255) / 256, 256, 0, s2>>>();           // launch 2 (s2)
    k_scan1<<<(EE + 255) / 256, 256, 0, s2>>>(ei);                   // launch 3 (s2)
    k_lstm_cl<<<BB, 256>>>(Whh1, TT, 1, 2);                          // launch 4: 16 clusters x 2 batches
    k_dedupe<<<1, MAXT, 0, s2>>>();                                  // launch 5 (s2)
    k_scan2<<<(EE + 255) / 256, 256, 0, s2>>>(ei);                   // launch 6 (s2)
    k_l1agg<<<256, HH, 0, s2>>>(data1);
    k_l1mat<<<128, HH, 0, s2>>>(data1, W1, b1);
    k_l2agg<<<64, HH, 0, s2>>>();
    k_l2mat<<<8, HH, 0, s2>>>(W2, b2);
    k_fw<<<1152, 64, 0, s2>>>(m1w, m2w);

    k_xpre2<<<4, 128>>>(Wih2, bih2, bhh2);
    k_lstm_cl<<<2, 256>>>(Whh2, BB, 2, 1);

    // join
    cudaEventRecord(evB, s2);
    cudaStreamWaitEvent(0, evB, 0);
    k_final<<<1, 512>>>(m1b, m2w, m2b, out);
}

// round 15
// speedup vs baseline: 1.0552x; 1.0552x over previous
#include <cuda_runtime.h>
#include <math.h>
#include <stdint.h>

#define NN 100000
#define EE 800000
#define HH 128
#define G4 512
#define TT 200
#define BB 32
#define INQ 64
#define MAXT 1024
#define MAXSLOTS (MAXT + 8)
#define MAXL1 131072

// ---------------- device scratch (no allocs allowed) ----------------
__device__ float g_deg[NN];
__device__ int   g_flag[NN];
__device__ int   g_cnt[4];          // 0=slotCount 1=tgtEdgeCount 2=l1EdgeCount
__device__ int   g_tgt_src[MAXT];
__device__ int   g_tgt_t[MAXT];
__device__ int   g_tgt_slot[MAXT];
__device__ int   g_nodeOfSlot[MAXSLOTS];
__device__ int   g_l1_src[MAXL1];
__device__ int   g_l1_slot[MAXL1];
__device__ float g_xagg[MAXSLOTS * HH];  // layer-1 aggregated raw features
__device__ float g_h1[MAXSLOTS * HH];    // layer-1 output per slot
__device__ float g_hagg[8 * HH];         // layer-2 aggregated h1 at targets
__device__ float g_dvec[9 * HH];
__device__ float g_fw[9 * HH];
__device__ float g_xpre[TT * BB * G4];   // LSTM1 input gates (x-part + biases)
__device__ float g_h1out[BB * HH];       // LSTM1 final hidden
__device__ float g_xpre2[BB * G4];       // LSTM2 input gates

// HW tanh (sm_75+): 1 MUFU op; sigmoid via tanh identity
__device__ __forceinline__ float ftanh(float x) {
    float r; asm("tanh.approx.f32 %0, %1;" : "=f"(r) : "f"(x)); return r;
}
__device__ __forceinline__ float fsig(float x) {
    return fmaf(ftanh(0.5f * x), 0.5f, 0.5f);
}

// ---------------- zero scratch ----------------
__global__ void k_zero() {
    int i = blockIdx.x * 256 + threadIdx.x;
    if (i < NN) { g_deg[i] = 0.f; g_flag[i] = 0; }
    if (i < MAXSLOTS * HH) g_xagg[i] = 0.f;
    if (i < 8 * HH) g_hagg[i] = 0.f;
    if (i < 4) g_cnt[i] = 0;
}

// ---------------- edge pass 1: degree histogram + edges into targets ----------------
__global__ void k_scan1(const int* __restrict__ ei) {
    int e = blockIdx.x * 256 + threadIdx.x;
    if (e >= EE) return;
    int d = ei[EE + e];
    atomicAdd(&g_deg[d], 1.0f);
    if (d <= 7000 && (d % 1000) == 0) {   // TARGET = {0,1000,...,7000}
        int ti = d / 1000;
        int p = atomicAdd(&g_cnt[1], 1);
        if (p < MAXT) { g_tgt_src[p] = ei[e]; g_tgt_t[p] = ti; }
    }
}

// ---------------- dedupe target-edge sources into slots; slots 0..7 = targets ----------------
__global__ void k_dedupe() {
    __shared__ int s_src[MAXT];
    __shared__ int s_first[MAXT];
    __shared__ int s_slot[MAXT];
    int i = threadIdx.x;
    int nT = g_cnt[1]; if (nT > MAXT) nT = MAXT;
    if (i < 8) { g_flag[i * 1000] = i + 1; g_nodeOfSlot[i] = i * 1000; }
    int s = (i < nT) ? g_tgt_src[i] : -1;
    s_src[i] = s;
    __syncthreads();
    int slot = -1, first = 0;
    if (i < nT) {
        #pragma unroll
        for (int k = 0; k < 8; k++) if (s == k * 1000) slot = k;
        if (slot < 0) {
            first = 1;
            for (int j = 0; j < i; j++) if (s_src[j] == s) { first = 0; break; }
        }
    }
    s_first[i] = (i < nT && slot < 0) ? first : 0;
    s_slot[i] = slot;
    __syncthreads();
    if (i < nT && slot < 0) {
        if (first) {
            int rank = 0;
            for (int j = 0; j < i; j++) rank += s_first[j];
            s_slot[i] = 8 + rank;
        } else {
            int j = 0; while (s_src[j] != s) j++;
            int rj = 0;
            for (int q = 0; q < j; q++) rj += s_first[q];
            s_slot[i] = 8 + rj;
        }
    }
    __syncthreads();
    if (i < nT) {
        g_tgt_slot[i] = s_slot[i];
        if (s_first[i]) { g_nodeOfSlot[s_slot[i]] = s_src[i]; g_flag[s_src[i]] = s_slot[i] + 1; }
    }
    if (i == 0) {
        int tot = 0;
        for (int j = 0; j < nT; j++) tot += s_first[j];
        g_cnt[0] = 8 + tot;
    }
}

// ---------------- edge pass 2: edges whose dst is in the 1-hop set ----------------
__global__ void k_scan2(const int* __restrict__ ei) {
    int e = blockIdx.x * 256 + threadIdx.x;
    if (e >= EE) return;
    int d = ei[EE + e];
    int f = g_flag[d];
    if (f > 0) {
        int p = atomicAdd(&g_cnt[2], 1);
        if (p < MAXL1) { g_l1_src[p] = ei[e]; g_l1_slot[p] = f - 1; }
    }
}

// ---------------- GCN layer 1: aggregate RAW features per slot (linearity fold) ----------------
__global__ void k_l1agg(const float* __restrict__ x) {
    int cnt = g_cnt[2]; if (cnt > MAXL1) cnt = MAXL1;
    for (int idx = blockIdx.x; idx < cnt; idx += gridDim.x) {
        int src = g_l1_src[idx], slot = g_l1_slot[idx];
        int dn = g_nodeOfSlot[slot];
        float norm = rsqrtf(g_deg[src] + 1.f) * rsqrtf(g_deg[dn] + 1.f);
        atomicAdd(&g_xagg[slot * HH + threadIdx.x], x[src * HH + threadIdx.x] * norm);
    }
}

// ---------------- GCN layer 1: (agg + self) @ W1 + b1, relu -> g_h1 ----------------
__global__ void k_l1mat(const float* __restrict__ x, const float* __restrict__ W1,
                        const float* __restrict__ b1) {
    __shared__ float xs[HH];
    int nslots = g_cnt[0];
    for (int slot = blockIdx.x; slot < nslots; slot += gridDim.x) {
        int node = g_nodeOfSlot[slot];
        float rs = rsqrtf(g_deg[node] + 1.f);
        float di2 = rs * rs;
        __syncthreads();
        xs[threadIdx.x] = g_xagg[slot * HH + threadIdx.x] + x[node * HH + threadIdx.x] * di2;
        __syncthreads();
        float acc = 0.f;
        #pragma unroll 8
        for (int k = 0; k < HH; k++) acc += xs[k] * W1[k * HH + threadIdx.x];
        g_h1[slot * HH + threadIdx.x] = fmaxf(acc + b1[threadIdx.x], 0.f);
    }
}

// ---------------- GCN layer 2: aggregate h1 at the 8 targets (linearity fold) ----------------
__global__ void k_l2agg() {
    int cnt = g_cnt[1]; if (cnt > MAXT) cnt = MAXT;
    for (int i = blockIdx.x; i < cnt; i += gridDim.x) {
        int t = g_tgt_t[i], s = g_tgt_src[i], slot = g_tgt_slot[i];
        int tn = t * 1000;
        float norm = rsqrtf(g_deg[s] + 1.f) * rsqrtf(g_deg[tn] + 1.f);
        atomicAdd(&g_hagg[t * HH + threadIdx.x], g_h1[slot * HH + threadIdx.x] * norm);
    }
}

// ---------------- GCN layer 2: (agg + self) @ W2 + b2, relu -> g_dvec[0:1024] ----------------
__global__ void k_l2mat(const float* __restrict__ W2, const float* __restrict__ b2) {
    __shared__ float hs[HH];
    int t = blockIdx.x, o = threadIdx.x;
    int tn = t * 1000;
    float rs = rsqrtf(g_deg[tn] + 1.f);
    float di2 = rs * rs;
    hs[o] = g_hagg[t * HH + o] + g_h1[t * HH + o] * di2;   // slot t == target t
    __syncthreads();
    float acc = 0.f;
    #pragma unroll 8
    for (int k = 0; k < HH; k++) acc += hs[k] * W2[k * HH + o];
    g_dvec[t * HH + o] = fmaxf(acc + b2[o], 0.f);
}

// ---------------- LSTM1 input GEMM: xpre[t*32+b, n] = data0[b,t,:] @ Wih1[n,:] + bih1+bhh1 ----------------
__global__ __launch_bounds__(256) void k_xpre(const float* __restrict__ data0,
                                              const float* __restrict__ Wih1,
                                              const float* __restrict__ bih1,
                                              const float* __restrict__ bhh1) {
    __shared__ float xs[64][65];
    __shared__ float ws[64][65];   // ws[k][j]
    int rowbase = blockIdx.x * 64;
    int colbase = blockIdx.y * 64;
    int tid = threadIdx.x;
    for (int idx = tid; idx < 64 * 64; idx += 256) {
        int i = idx >> 6, k = idx & 63;
        int r = rowbase + i, b = r & 31, t = r >> 5;
        xs[i][k] = data0[(b * TT + t) * INQ + k];
    }
    for (int idx = tid; idx < 64 * 64; idx += 256) {
        int j = idx >> 6, k = idx & 63;
        ws[k][j] = Wih1[(colbase + j) * INQ + k];
    }
    __syncthreads();
    int tx = tid & 15, ty = tid >> 4;
    float acc[4][4] = {};
    #pragma unroll 8
    for (int k = 0; k < 64; k++) {
        float a[4], bb[4];
        #pragma unroll
        for (int u = 0; u < 4; u++) a[u] = xs[ty * 4 + u][k];
        #pragma unroll
        for (int v = 0; v < 4; v++) bb[v] = ws[k][tx * 4 + v];
        #pragma unroll
        for (int u = 0; u < 4; u++)
            #pragma unroll
            for (int v = 0; v < 4; v++) acc[u][v] = fmaf(a[u], bb[v], acc[u][v]);
    }
    #pragma unroll
    for (int u = 0; u < 4; u++) {
        int r = rowbase + ty * 4 + u;
        #pragma unroll
        for (int v = 0; v < 4; v++) {
            int n = colbase + tx * 4 + v;
            g_xpre[r * G4 + n] = acc[u][v] + bih1[n] + bhh1[n];
        }
    }
}

// ---------------- LSTM recurrence: 2-CTA cluster; 512 threads; 2 threads per gate row ----------
// Lane layout: ko = tid&1 (column half), gt = (tid>>1)&3, m = tid>>3; hidx = rank*64+m.
// Each thread owns 64 weight columns (32 regs): 32 own-half + 32 peer-half. Phase 1 (own,
// local) hides DSMEM transfer; wait; phase 2 (peer). Pair shfl_xor(1) combines halves,
// quad shfl gathers transformed gates. 16 warps = 4/SMSP for latency hiding.
#define MBAR_WAIT_CL(addr, parity) do {                                            \
    asm volatile("{\n\t.reg .pred P;\n\t"                                          \
        "WL_%=:\n\t"                                                               \
        "mbarrier.try_wait.parity.acquire.cluster.shared::cta.b64 P, [%0], %1, 0x989680;\n\t"\
        "@P bra.uni WD_%=;\n\t"                                                    \
        "bra.uni WL_%=;\n\t"                                                       \
        "WD_%=:\n\t}"                                                              \
        :: "r"(addr), "r"(parity) : "memory");                                     \
} while (0)

__global__ __launch_bounds__(512, 1) __cluster_dims__(2, 1, 1)
void k_lstm_cl(const float* __restrict__ Whh, int steps, int which) {
    __shared__ __align__(16) float sh_h[2][HH];
    __shared__ __align__(8) unsigned long long smb[2];
    int tid = threadIdx.x;
    int rank = (int)(blockIdx.x & 1);
    int b = (int)(blockIdx.x >> 1);
    int ko = tid & 1;             // column half within each 64-chunk
    int gt = (tid >> 1) & 3;      // gate type 0..3 (i,f,g,o)
    int m  = tid >> 3;            // h-offset within my chunk (0..63)
    int hidx = (rank << 6) + m;   // global h index
    int row  = gt * HH + hidx;    // gate row this thread (half-)computes

    // one-time: 32 own-half + 32 peer-half weight columns into registers (static indices)
    unsigned long long wqA[16], wqB[16];
    {
        const float4* w4own = (const float4*)(Whh + row * HH + (rank << 6) + (ko << 5));
        const float4* w4rem = (const float4*)(Whh + row * HH + ((1 ^ rank) << 6) + (ko << 5));
        #pragma unroll
        for (int q = 0; q < 8; q++) {
            float4 w = __ldg(&w4own[q]);
            asm("mov.b64 %0, {%1,%2};" : "=l"(wqA[2 * q])     : "f"(w.x), "f"(w.y));
            asm("mov.b64 %0, {%1,%2};" : "=l"(wqA[2 * q + 1]) : "f"(w.z), "f"(w.w));
        }
        #pragma unroll
        for (int q = 0; q < 8; q++) {
            float4 w = __ldg(&w4rem[q]);
            asm("mov.b64 %0, {%1,%2};" : "=l"(wqB[2 * q])     : "f"(w.x), "f"(w.y));
            asm("mov.b64 %0, {%1,%2};" : "=l"(wqB[2 * q + 1]) : "f"(w.z), "f"(w.w));
        }
    }

    if (tid < HH) sh_h[0][tid] = 0.f;
    if (tid == 0) {
        uint32_t b0 = (uint32_t)__cvta_generic_to_shared(&smb[0]);
        uint32_t b1 = (uint32_t)__cvta_generic_to_shared(&smb[1]);
        asm volatile("mbarrier.init.shared.b64 [%0], %1;" :: "r"(b0), "r"(64u));
        asm volatile("mbarrier.init.shared.b64 [%0], %1;" :: "r"(b1), "r"(64u));
    }

    uint32_t sh_base = (uint32_t)__cvta_generic_to_shared(&sh_h[0][0]);
    uint32_t lb0 = (uint32_t)__cvta_generic_to_shared(&smb[0]);
    uint32_t lb1 = (uint32_t)__cvta_generic_to_shared(&smb[1]);
    uint32_t lh0 = (uint32_t)__cvta_generic_to_shared(&sh_h[0][hidx]);
    uint32_t lh1 = (uint32_t)__cvta_generic_to_shared(&sh_h[1][hidx]);
    uint32_t peer = 1u ^ (uint32_t)rank;
    uint32_t rh0, rh1, rb0, rb1;
    asm("mapa.shared::cluster.u32 %0, %1, %2;" : "=r"(rh0) : "r"(lh0), "r"(peer));
    asm("mapa.shared::cluster.u32 %0, %1, %2;" : "=r"(rh1) : "r"(lh1), "r"(peer));
    asm("mapa.shared::cluster.u32 %0, %1, %2;" : "=r"(rb0) : "r"(lb0), "r"(peer));
    asm("mapa.shared::cluster.u32 %0, %1, %2;" : "=r"(rb1) : "r"(lb1), "r"(peer));
    __syncthreads();
    asm volatile("barrier.cluster.arrive.aligned;" ::: "memory");
    asm volatile("barrier.cluster.wait.aligned;" ::: "memory");

    int ph0 = 0, ph1 = 0;
    float c = 0.f;
    int lane = tid & 31;
    int qb8 = lane & ~7;                           // base lane of my (m) group: bits 3-4 kept
    uint32_t own_off = (uint32_t)((rank << 8) + (ko << 7));   // my 32-col slice of own half
    uint32_t rem_off = (uint32_t)(((1 ^ rank) << 8) + (ko << 7));
    float accn = (which == 1) ? g_xpre[b * G4 + row] : g_xpre2[row];
    for (int s = 0; s < steps; s++) {
        int buf = s & 1;
        float acc = accn;
        if (s + 1 < steps)
            accn = (which == 1) ? g_xpre[((s + 1) * BB + b) * G4 + row]
                                : g_xpre2[(s + 1) * G4 + row];

        uint32_t hb = sh_base + ((uint32_t)buf << 9);
        unsigned long long a0 = 0ull, a1 = 0ull;

        // phase 1: OWN half slice (written locally last step; no cross-CTA dependency)
        #pragma unroll
        for (int q = 0; q < 8; q++) {
            unsigned long long h01, h23;
            asm volatile("ld.shared.v2.u64 {%0,%1}, [%2];"
                         : "=l"(h01), "=l"(h23) : "r"(hb + own_off + q * 16));
            asm("fma.rn.f32x2 %0, %1, %2, %0;" : "+l"(a0) : "l"(wqA[2 * q]),     "l"(h01));
            asm("fma.rn.f32x2 %0, %1, %2, %0;" : "+l"(a1) : "l"(wqA[2 * q + 1]), "l"(h23));
        }

        // wait for peer half (hidden behind phase 1)
        if (s > 0) {
            if (buf) { MBAR_WAIT_CL(lb1, ph1); ph1 ^= 1; }
            else     { MBAR_WAIT_CL(lb0, ph0); ph0 ^= 1; }
        }

        // phase 2: PEER half slice
        #pragma unroll
        for (int q = 0; q < 8; q++) {
            unsigned long long h01, h23;
            asm volatile("ld.shared.v2.u64 {%0,%1}, [%2];"
                         : "=l"(h01), "=l"(h23) : "r"(hb + rem_off + q * 16));
            asm("fma.rn.f32x2 %0, %1, %2, %0;" : "+l"(a0) : "l"(wqB[2 * q]),     "l"(h01));
            asm("fma.rn.f32x2 %0, %1, %2, %0;" : "+l"(a1) : "l"(wqB[2 * q + 1]), "l"(h23));
        }

        asm("add.rn.f32x2 %0, %0, %1;" : "+l"(a0) : "l"(a1));
        float x0, y0;
        asm("mov.b64 {%0,%1}, %2;" : "=f"(x0), "=f"(y0) : "l"(a0));
        float vh = x0 + y0;
        // pair combine: two column-halves of the same row sit in adjacent lanes (ko = bit0)
        float v = acc + (vh + __shfl_xor_sync(0xffffffffu, vh, 1));

        // transform own gate FIRST (1 MUFU), then gather transformed gates for my m
        float t = (gt == 2) ? ftanh(v) : fsig(v);
        float t0 = __shfl_sync(0xffffffffu, t, qb8 + 0);   // sig(i)
        float t1 = __shfl_sync(0xffffffffu, t, qb8 + 2);   // sig(f)
        float t2 = __shfl_sync(0xffffffffu, t, qb8 + 4);   // tanh(g)
        float t3 = __shfl_sync(0xffffffffu, t, qb8 + 6);   // sig(o)

        // redundant (consistent) c/h update in every lane of the octet
        c = t1 * c + t0 * t2;
        float h = t3 * ftanh(c);

        if (s + 1 < steps) {
            int bn = (s + 1) & 1;
            if ((tid & 7) == 0) {      // gt==0 && ko==0: one sender per h-index
                sh_h[bn][hidx] = h;
                uint32_t rg = bn ? rh1 : rh0;
                uint32_t rb = bn ? rb1 : rb0;
                asm volatile("st.shared::cluster.f32 [%0], %1;" :: "r"(rg), "f"(h) : "memory");
                asm volatile("mbarrier.arrive.release.cluster.shared::cluster.b64 _, [%0];"
                             :: "r"(rb) : "memory");
            }
            __syncthreads();   // local sh_h[bn] visible to all warps' next phase-1
        } else {
            if ((tid & 7) == 0) {
                if (which == 1) g_h1out[b * HH + hidx] = h;
                else            g_dvec[8 * HH + hidx] = h;
            }
        }
    }
}

// ---------------- LSTM2 input GEMM: xpre2[s, n] = h1out[s,:] @ Wih2[n,:] + biases ----------------
__global__ __launch_bounds__(128) void k_xpre2(const float* __restrict__ Wih2,
                                               const float* __restrict__ bih2,
                                               const float* __restrict__ bhh2) {
    __shared__ float hh[BB * HH];
    int tid = threadIdx.x;
    for (int idx = tid; idx < BB * HH; idx += 128) hh[idx] = g_h1out[idx];
    __syncthreads();
    int n = blockIdx.x * 128 + tid;
    float4 wreg[32];
    const float4* w4 = (const float4*)(Wih2 + n * HH);
    #pragma unroll
    for (int kk = 0; kk < 32; kk++) wreg[kk] = __ldg(&w4[kk]);
    float bias = bih2[n] + bhh2[n];
    for (int s = 0; s < BB; s++) {
        const float4* h4 = (const float4*)(hh + s * HH);
        float a0 = 0.f, a1 = 0.f, a2 = 0.f, a3 = 0.f;
        #pragma unroll
        for (int kk = 0; kk < 32; kk++) {
            float4 h = h4[kk];
            a0 = fmaf(wreg[kk].x, h.x, a0); a1 = fmaf(wreg[kk].y, h.y, a1);
            a2 = fmaf(wreg[kk].z, h.z, a2); a3 = fmaf(wreg[kk].w, h.w, a3);
        }
        g_xpre2[s * G4 + n] = bias + ((a0 + a1) + (a2 + a3));
    }
}

// ---------------- MLP head: fuse m1_w @ m2_w (no nonlinearity in head) ----------------
__global__ void k_fw(const float* __restrict__ m1w, const float* __restrict__ m2w) {
    int i = blockIdx.x;
    float s = 0.f;
    for (int j = threadIdx.x; j < 576; j += 64) s += m1w[i * 576 + j] * m2w[j];
    #pragma unroll
    for (int off = 16; off > 0; off >>= 1) s += __shfl_down_sync(0xffffffffu, s, off);
    __shared__ float sm[2];
    if ((threadIdx.x & 31) == 0) sm[threadIdx.x >> 5] = s;
    __syncthreads();
    if (threadIdx.x == 0) g_fw[i] = sm[0] + sm[1];
}

__global__ void k_final(const float* __restrict__ m1b, const float* __restrict__ m2w,
                        const float* __restrict__ m2b, float* __restrict__ out) {
    __shared__ float red[512];
    float s = 0.f;
    for (int i = threadIdx.x; i < 9 * HH; i += 512) s += g_dvec[i] * g_fw[i];
    for (int j = threadIdx.x; j < 576; j += 512) s += m1b[j] * m2w[j];
    red[threadIdx.x] = s;
    __syncthreads();
    for (int st = 256; st > 0; st >>= 1) {
        if (threadIdx.x < st) red[threadIdx.x] += red[threadIdx.x + st];
        __syncthreads();
    }
    if (threadIdx.x == 0) out[0] = red[0] + m2b[0];
}

// ---------------- launch ----------------
extern "C" void kernel_launch(void* const* d_in, const int* in_sizes, int n_in,
                              void* d_out, int out_size) {
    const float* data0 = (const float*)d_in[0];
    const float* data1 = (const float*)d_in[1];
    const int*   ei    = (const int*)d_in[2];
    const float* W1   = (const float*)d_in[3];
    const float* b1   = (const float*)d_in[4];
    const float* W2   = (const float*)d_in[5];
    const float* b2   = (const float*)d_in[6];
    const float* Wih1 = (const float*)d_in[7];
    const float* Whh1 = (const float*)d_in[8];
    const float* bih1 = (const float*)d_in[9];
    const float* bhh1 = (const float*)d_in[10];
    const float* Wih2 = (const float*)d_in[11];
    const float* Whh2 = (const float*)d_in[12];
    const float* bih2 = (const float*)d_in[13];
    const float* bhh2 = (const float*)d_in[14];
    const float* m1w  = (const float*)d_in[15];
    const float* m1b  = (const float*)d_in[16];
    const float* m2w  = (const float*)d_in[17];
    const float* m2b  = (const float*)d_in[18];
    float* out = (float*)d_out;

    static cudaStream_t s2 = nullptr;
    static cudaEvent_t evA = nullptr, evB = nullptr;
    if (!s2) {
        cudaStreamCreateWithFlags(&s2, cudaStreamNonBlocking);
        cudaEventCreateWithFlags(&evA, cudaEventDisableTiming);
        cudaEventCreateWithFlags(&evB, cudaEventDisableTiming);
    }

    // fork: GCN chain + head-weight fold run on s2, LSTM chain on default stream.
    // Host launch order puts k_lstm_cl 4th so ncu's fixed capture slot profiles it.
    cudaEventRecord(evA, 0);
    cudaStreamWaitEvent(s2, evA, 0);

    k_xpre<<<dim3(100, 8), 256>>>(data0, Wih1, bih1, bhh1);          // launch 1 (default)
    k_zero<<<(MAXSLOTS * HH + 255) / 256, 256, 0, s2>>>();           // launch 2 (s2)
    k_scan1<<<(EE + 255) / 256, 256, 0, s2>>>(ei);                   // launch 3 (s2)
    k_lstm_cl<<<2 * BB, 512>>>(Whh1, TT, 1);                         // launch 4 (default) <- ncu slot
    k_dedupe<<<1, MAXT, 0, s2>>>();                                  // launch 5 (s2)
    k_scan2<<<(EE + 255) / 256, 256, 0, s2>>>(ei);                   // launch 6 (s2)
    k_l1agg<<<256, HH, 0, s2>>>(data1);
    k_l1mat<<<128, HH, 0, s2>>>(data1, W1, b1);
    k_l2agg<<<64, HH, 0, s2>>>();
    k_l2mat<<<8, HH, 0, s2>>>(W2, b2);
    k_fw<<<1152, 64, 0, s2>>>(m1w, m2w);

    k_xpre2<<<4, 128>>>(Wih2, bih2, bhh2);
    k_lstm_cl<<<2, 512>>>(Whh2, BB, 2);

    // join
    cudaEventRecord(evB, s2);
    cudaStreamWaitEvent(0, evB, 0);
    k_final<<<1, 512>>>(m1b, m2w, m2b, out);
}

// round 16
// speedup vs baseline: 1.2554x; 1.1898x over previous
#include <cuda_runtime.h>
#include <math.h>
#include <stdint.h>

#define NN 100000
#define EE 800000
#define HH 128
#define G4 512
#define TT 200
#define BB 32
#define INQ 64
#define MAXT 1024
#define MAXSLOTS (MAXT + 8)
#define MAXL1 131072

// ---------------- device scratch (no allocs allowed) ----------------
__device__ float g_deg[NN];
__device__ int   g_flag[NN];
__device__ int   g_cnt[4];          // 0=slotCount 1=tgtEdgeCount 2=l1EdgeCount
__device__ int   g_tgt_src[MAXT];
__device__ int   g_tgt_t[MAXT];
__device__ int   g_tgt_slot[MAXT];
__device__ int   g_nodeOfSlot[MAXSLOTS];
__device__ int   g_l1_src[MAXL1];
__device__ int   g_l1_slot[MAXL1];
__device__ float g_xagg[MAXSLOTS * HH];  // layer-1 aggregated raw features
__device__ float g_h1[MAXSLOTS * HH];    // layer-1 output per slot
__device__ float g_hagg[8 * HH];         // layer-2 aggregated h1 at targets
__device__ float g_dvec[9 * HH];
__device__ float g_fw[9 * HH];
__device__ float g_xpre[TT * BB * G4];   // LSTM1 input gates (x-part + biases)
__device__ float g_h1out[BB * HH];       // LSTM1 final hidden
__device__ float g_xpre2[BB * G4];       // LSTM2 input gates

// HW tanh (sm_75+): 1 MUFU op; sigmoid via tanh identity
__device__ __forceinline__ float ftanh(float x) {
    float r; asm("tanh.approx.f32 %0, %1;" : "=f"(r) : "f"(x)); return r;
}
__device__ __forceinline__ float fsig(float x) {
    return fmaf(ftanh(0.5f * x), 0.5f, 0.5f);
}

// ---------------- zero scratch ----------------
__global__ void k_zero() {
    int i = blockIdx.x * 256 + threadIdx.x;
    if (i < NN) { g_deg[i] = 0.f; g_flag[i] = 0; }
    if (i < MAXSLOTS * HH) g_xagg[i] = 0.f;
    if (i < 8 * HH) g_hagg[i] = 0.f;
    if (i < 4) g_cnt[i] = 0;
}

// ---------------- edge pass 1: degree histogram + edges into targets ----------------
__global__ void k_scan1(const int* __restrict__ ei) {
    int e = blockIdx.x * 256 + threadIdx.x;
    if (e >= EE) return;
    int d = ei[EE + e];
    atomicAdd(&g_deg[d], 1.0f);
    if (d <= 7000 && (d % 1000) == 0) {   // TARGET = {0,1000,...,7000}
        int ti = d / 1000;
        int p = atomicAdd(&g_cnt[1], 1);
        if (p < MAXT) { g_tgt_src[p] = ei[e]; g_tgt_t[p] = ti; }
    }
}

// ---------------- dedupe target-edge sources into slots; slots 0..7 = targets ----------------
__global__ void k_dedupe() {
    __shared__ int s_src[MAXT];
    __shared__ int s_first[MAXT];
    __shared__ int s_slot[MAXT];
    int i = threadIdx.x;
    int nT = g_cnt[1]; if (nT > MAXT) nT = MAXT;
    if (i < 8) { g_flag[i * 1000] = i + 1; g_nodeOfSlot[i] = i * 1000; }
    int s = (i < nT) ? g_tgt_src[i] : -1;
    s_src[i] = s;
    __syncthreads();
    int slot = -1, first = 0;
    if (i < nT) {
        #pragma unroll
        for (int k = 0; k < 8; k++) if (s == k * 1000) slot = k;
        if (slot < 0) {
            first = 1;
            for (int j = 0; j < i; j++) if (s_src[j] == s) { first = 0; break; }
        }
    }
    s_first[i] = (i < nT && slot < 0) ? first : 0;
    s_slot[i] = slot;
    __syncthreads();
    if (i < nT && slot < 0) {
        if (first) {
            int rank = 0;
            for (int j = 0; j < i; j++) rank += s_first[j];
            s_slot[i] = 8 + rank;
        } else {
            int j = 0; while (s_src[j] != s) j++;
            int rj = 0;
            for (int q = 0; q < j; q++) rj += s_first[q];
            s_slot[i] = 8 + rj;
        }
    }
    __syncthreads();
    if (i < nT) {
        g_tgt_slot[i] = s_slot[i];
        if (s_first[i]) { g_nodeOfSlot[s_slot[i]] = s_src[i]; g_flag[s_src[i]] = s_slot[i] + 1; }
    }
    if (i == 0) {
        int tot = 0;
        for (int j = 0; j < nT; j++) tot += s_first[j];
        g_cnt[0] = 8 + tot;
    }
}

// ---------------- edge pass 2: edges whose dst is in the 1-hop set ----------------
__global__ void k_scan2(const int* __restrict__ ei) {
    int e = blockIdx.x * 256 + threadIdx.x;
    if (e >= EE) return;
    int d = ei[EE + e];
    int f = g_flag[d];
    if (f > 0) {
        int p = atomicAdd(&g_cnt[2], 1);
        if (p < MAXL1) { g_l1_src[p] = ei[e]; g_l1_slot[p] = f - 1; }
    }
}

// ---------------- GCN layer 1: aggregate RAW features per slot (linearity fold) ----------------
__global__ void k_l1agg(const float* __restrict__ x) {
    int cnt = g_cnt[2]; if (cnt > MAXL1) cnt = MAXL1;
    for (int idx = blockIdx.x; idx < cnt; idx += gridDim.x) {
        int src = g_l1_src[idx], slot = g_l1_slot[idx];
        int dn = g_nodeOfSlot[slot];
        float norm = rsqrtf(g_deg[src] + 1.f) * rsqrtf(g_deg[dn] + 1.f);
        atomicAdd(&g_xagg[slot * HH + threadIdx.x], x[src * HH + threadIdx.x] * norm);
    }
}

// ---------------- GCN layer 1: (agg + self) @ W1 + b1, relu -> g_h1 ----------------
__global__ void k_l1mat(const float* __restrict__ x, const float* __restrict__ W1,
                        const float* __restrict__ b1) {
    __shared__ float xs[HH];
    int nslots = g_cnt[0];
    for (int slot = blockIdx.x; slot < nslots; slot += gridDim.x) {
        int node = g_nodeOfSlot[slot];
        float rs = rsqrtf(g_deg[node] + 1.f);
        float di2 = rs * rs;
        __syncthreads();
        xs[threadIdx.x] = g_xagg[slot * HH + threadIdx.x] + x[node * HH + threadIdx.x] * di2;
        __syncthreads();
        float acc = 0.f;
        #pragma unroll 8
        for (int k = 0; k < HH; k++) acc += xs[k] * W1[k * HH + threadIdx.x];
        g_h1[slot * HH + threadIdx.x] = fmaxf(acc + b1[threadIdx.x], 0.f);
    }
}

// ---------------- GCN layer 2: aggregate h1 at the 8 targets (linearity fold) ----------------
__global__ void k_l2agg() {
    int cnt = g_cnt[1]; if (cnt > MAXT) cnt = MAXT;
    for (int i = blockIdx.x; i < cnt; i += gridDim.x) {
        int t = g_tgt_t[i], s = g_tgt_src[i], slot = g_tgt_slot[i];
        int tn = t * 1000;
        float norm = rsqrtf(g_deg[s] + 1.f) * rsqrtf(g_deg[tn] + 1.f);
        atomicAdd(&g_hagg[t * HH + threadIdx.x], g_h1[slot * HH + threadIdx.x] * norm);
    }
}

// ---------------- GCN layer 2: (agg + self) @ W2 + b2, relu -> g_dvec[0:1024] ----------------
__global__ void k_l2mat(const float* __restrict__ W2, const float* __restrict__ b2) {
    __shared__ float hs[HH];
    int t = blockIdx.x, o = threadIdx.x;
    int tn = t * 1000;
    float rs = rsqrtf(g_deg[tn] + 1.f);
    float di2 = rs * rs;
    hs[o] = g_hagg[t * HH + o] + g_h1[t * HH + o] * di2;   // slot t == target t
    __syncthreads();
    float acc = 0.f;
    #pragma unroll 8
    for (int k = 0; k < HH; k++) acc += hs[k] * W2[k * HH + o];
    g_dvec[t * HH + o] = fmaxf(acc + b2[o], 0.f);
}

// ---------------- LSTM1 input GEMM: xpre[t*32+b, n] = data0[b,t,:] @ Wih1[n,:] + bih1+bhh1 ----------------
__global__ __launch_bounds__(256) void k_xpre(const float* __restrict__ data0,
                                              const float* __restrict__ Wih1,
                                              const float* __restrict__ bih1,
                                              const float* __restrict__ bhh1) {
    __shared__ float xs[64][65];
    __shared__ float ws[64][65];   // ws[k][j]
    int rowbase = blockIdx.x * 64;
    int colbase = blockIdx.y * 64;
    int tid = threadIdx.x;
    for (int idx = tid; idx < 64 * 64; idx += 256) {
        int i = idx >> 6, k = idx & 63;
        int r = rowbase + i, b = r & 31, t = r >> 5;
        xs[i][k] = data0[(b * TT + t) * INQ + k];
    }
    for (int idx = tid; idx < 64 * 64; idx += 256) {
        int j = idx >> 6, k = idx & 63;
        ws[k][j] = Wih1[(colbase + j) * INQ + k];
    }
    __syncthreads();
    int tx = tid & 15, ty = tid >> 4;
    float acc[4][4] = {};
    #pragma unroll 8
    for (int k = 0; k < 64; k++) {
        float a[4], bb[4];
        #pragma unroll
        for (int u = 0; u < 4; u++) a[u] = xs[ty * 4 + u][k];
        #pragma unroll
        for (int v = 0; v < 4; v++) bb[v] = ws[k][tx * 4 + v];
        #pragma unroll
        for (int u = 0; u < 4; u++)
            #pragma unroll
            for (int v = 0; v < 4; v++) acc[u][v] = fmaf(a[u], bb[v], acc[u][v]);
    }
    #pragma unroll
    for (int u = 0; u < 4; u++) {
        int r = rowbase + ty * 4 + u;
        #pragma unroll
        for (int v = 0; v < 4; v++) {
            int n = colbase + tx * 4 + v;
            g_xpre[r * G4 + n] = acc[u][v] + bih1[n] + bhh1[n];
        }
    }
}

// ---------------- LSTM recurrence: 2-CTA cluster; quad-lane gates; split-phase matvec ----------
// EXACT structure of the measured-best (R12) kernel; single change: try_wait has NO sleep
// hint (plain polling). A/B test of suspend-entry cost on the ~200-iteration wait path.
#define MBAR_WAIT_CL(addr, parity) do {                                            \
    asm volatile("{\n\t.reg .pred P;\n\t"                                          \
        "WL_%=:\n\t"                                                               \
        "mbarrier.try_wait.parity.acquire.cluster.shared::cta.b64 P, [%0], %1;\n\t"\
        "@P bra.uni WD_%=;\n\t"                                                    \
        "bra.uni WL_%=;\n\t"                                                       \
        "WD_%=:\n\t}"                                                              \
        :: "r"(addr), "r"(parity) : "memory");                                     \
} while (0)

__global__ __launch_bounds__(256, 1) __cluster_dims__(2, 1, 1)
void k_lstm_cl(const float* __restrict__ Whh, int steps, int which) {
    __shared__ __align__(16) float sh_h[2][HH];
    __shared__ __align__(8) unsigned long long smb[2];
    int tid = threadIdx.x;
    int rank = (int)(blockIdx.x & 1);
    int b = (int)(blockIdx.x >> 1);
    int gt = tid & 3;             // gate type 0..3 (i,f,g,o)
    int m  = tid >> 2;            // h-offset within my chunk (0..63)
    int hidx = (rank << 6) + m;   // global h index
    int row  = gt * HH + hidx;    // gate row this thread computes

    // one-time: weight row into registers, split own/peer halves with STATIC reg indices
    unsigned long long wqA[32], wqB[32];
    {
        const float4* w4own = (const float4*)(Whh + row * HH + (rank << 6));
        const float4* w4rem = (const float4*)(Whh + row * HH + ((1 ^ rank) << 6));
        #pragma unroll
        for (int q = 0; q < 16; q++) {
            float4 w = __ldg(&w4own[q]);
            asm("mov.b64 %0, {%1,%2};" : "=l"(wqA[2 * q])     : "f"(w.x), "f"(w.y));
            asm("mov.b64 %0, {%1,%2};" : "=l"(wqA[2 * q + 1]) : "f"(w.z), "f"(w.w));
        }
        #pragma unroll
        for (int q = 0; q < 16; q++) {
            float4 w = __ldg(&w4rem[q]);
            asm("mov.b64 %0, {%1,%2};" : "=l"(wqB[2 * q])     : "f"(w.x), "f"(w.y));
            asm("mov.b64 %0, {%1,%2};" : "=l"(wqB[2 * q + 1]) : "f"(w.z), "f"(w.w));
        }
    }

    if (tid < HH) sh_h[0][tid] = 0.f;
    if (tid == 0) {
        uint32_t b0 = (uint32_t)__cvta_generic_to_shared(&smb[0]);
        uint32_t b1 = (uint32_t)__cvta_generic_to_shared(&smb[1]);
        asm volatile("mbarrier.init.shared.b64 [%0], %1;" :: "r"(b0), "r"(8u));
        asm volatile("mbarrier.init.shared.b64 [%0], %1;" :: "r"(b1), "r"(8u));
    }

    uint32_t sh_base = (uint32_t)__cvta_generic_to_shared(&sh_h[0][0]);
    uint32_t lb0 = (uint32_t)__cvta_generic_to_shared(&smb[0]);
    uint32_t lb1 = (uint32_t)__cvta_generic_to_shared(&smb[1]);
    uint32_t lh0 = (uint32_t)__cvta_generic_to_shared(&sh_h[0][hidx]);
    uint32_t lh1 = (uint32_t)__cvta_generic_to_shared(&sh_h[1][hidx]);
    uint32_t peer = 1u ^ (uint32_t)rank;
    uint32_t rh0, rh1, rb0, rb1;
    asm("mapa.shared::cluster.u32 %0, %1, %2;" : "=r"(rh0) : "r"(lh0), "r"(peer));
    asm("mapa.shared::cluster.u32 %0, %1, %2;" : "=r"(rh1) : "r"(lh1), "r"(peer));
    asm("mapa.shared::cluster.u32 %0, %1, %2;" : "=r"(rb0) : "r"(lb0), "r"(peer));
    asm("mapa.shared::cluster.u32 %0, %1, %2;" : "=r"(rb1) : "r"(lb1), "r"(peer));
    __syncthreads();
    asm volatile("barrier.cluster.arrive.aligned;" ::: "memory");
    asm volatile("barrier.cluster.wait.aligned;" ::: "memory");

    int ph0 = 0, ph1 = 0;
    float c = 0.f;
    int qbase = (tid & 31) & ~3;               // quad base lane within warp
    uint32_t own_off = (uint32_t)(rank << 8);  // own half byte offset (64 floats)
    uint32_t rem_off = own_off ^ 256u;         // peer half byte offset
    float accn = (which == 1) ? g_xpre[b * G4 + row] : g_xpre2[row];
    for (int s = 0; s < steps; s++) {
        int buf = s & 1;
        float acc = accn;
        if (s + 1 < steps)
            accn = (which == 1) ? g_xpre[((s + 1) * BB + b) * G4 + row]
                                : g_xpre2[(s + 1) * G4 + row];

        uint32_t hb = sh_base + ((uint32_t)buf << 9);
        unsigned long long a0 = 0ull, a1 = 0ull, a2 = 0ull, a3 = 0ull;

        // phase 1: OWN half (written locally last step; no cross-CTA dependency)
        #pragma unroll
        for (int q = 0; q < 16; q++) {
            unsigned long long h01, h23;
            asm volatile("ld.shared.v2.u64 {%0,%1}, [%2];"
                         : "=l"(h01), "=l"(h23) : "r"(hb + own_off + q * 16));
            asm("fma.rn.f32x2 %0, %1, %2, %0;" : "+l"(a0) : "l"(wqA[2 * q]),     "l"(h01));
            asm("fma.rn.f32x2 %0, %1, %2, %0;" : "+l"(a1) : "l"(wqA[2 * q + 1]), "l"(h23));
        }

        // wait for peer half (hidden behind phase 1)
        if (s > 0) {
            if (buf) { MBAR_WAIT_CL(lb1, ph1); ph1 ^= 1; }
            else     { MBAR_WAIT_CL(lb0, ph0); ph0 ^= 1; }
        }

        // phase 2: PEER half
        #pragma unroll
        for (int q = 0; q < 16; q++) {
            unsigned long long h01, h23;
            asm volatile("ld.shared.v2.u64 {%0,%1}, [%2];"
                         : "=l"(h01), "=l"(h23) : "r"(hb + rem_off + q * 16));
            asm("fma.rn.f32x2 %0, %1, %2, %0;" : "+l"(a2) : "l"(wqB[2 * q]),     "l"(h01));
            asm("fma.rn.f32x2 %0, %1, %2, %0;" : "+l"(a3) : "l"(wqB[2 * q + 1]), "l"(h23));
        }

        asm("add.rn.f32x2 %0, %0, %1;" : "+l"(a0) : "l"(a2));
        asm("add.rn.f32x2 %0, %0, %1;" : "+l"(a1) : "l"(a3));
        float x0, y0, x1, y1;
        asm("mov.b64 {%0,%1}, %2;" : "=f"(x0), "=f"(y0) : "l"(a0));
        asm("mov.b64 {%0,%1}, %2;" : "=f"(x1), "=f"(y1) : "l"(a1));
        float v = acc + ((x0 + y0) + (x1 + y1));

        // quad gather: all 4 gate values for my m (adjacent lanes)
        float gi = __shfl_sync(0xffffffffu, v, qbase + 0);
        float gf = __shfl_sync(0xffffffffu, v, qbase + 1);
        float gg = __shfl_sync(0xffffffffu, v, qbase + 2);
        float go = __shfl_sync(0xffffffffu, v, qbase + 3);

        // redundant (consistent) c/h update in every lane of the quad
        c = fsig(gf) * c + fsig(gi) * ftanh(gg);
        float h = fsig(go) * ftanh(c);

        if (s + 1 < steps) {
            int bn = (s + 1) & 1;
            if (gt == 0) {
                sh_h[bn][hidx] = h;
                uint32_t rg = bn ? rh1 : rh0;
                asm volatile("st.shared::cluster.f32 [%0], %1;" :: "r"(rg), "f"(h) : "memory");
            }
            __syncwarp();   // intra-warp: all 8 senders' stores ordered before elected arrive
            if ((tid & 31) == 0) {
                uint32_t rb = bn ? rb1 : rb0;
                asm volatile("mbarrier.arrive.release.cluster.shared::cluster.b64 _, [%0];"
                             :: "r"(rb) : "memory");
            }
            __syncthreads();   // local sh_h[bn] visible to all warps' next phase-1
        } else {
            if (gt == 0) {
                if (which == 1) g_h1out[b * HH + hidx] = h;
                else            g_dvec[8 * HH + hidx] = h;
            }
        }
    }
}

// ---------------- LSTM2 input GEMM: xpre2[s, n] = h1out[s,:] @ Wih2[n,:] + biases ----------------
__global__ __launch_bounds__(128) void k_xpre2(const float* __restrict__ Wih2,
                                               const float* __restrict__ bih2,
                                               const float* __restrict__ bhh2) {
    __shared__ float hh[BB * HH];
    int tid = threadIdx.x;
    for (int idx = tid; idx < BB * HH; idx += 128) hh[idx] = g_h1out[idx];
    __syncthreads();
    int n = blockIdx.x * 128 + tid;
    float4 wreg[32];
    const float4* w4 = (const float4*)(Wih2 + n * HH);
    #pragma unroll
    for (int kk = 0; kk < 32; kk++) wreg[kk] = __ldg(&w4[kk]);
    float bias = bih2[n] + bhh2[n];
    for (int s = 0; s < BB; s++) {
        const float4* h4 = (const float4*)(hh + s * HH);
        float a0 = 0.f, a1 = 0.f, a2 = 0.f, a3 = 0.f;
        #pragma unroll
        for (int kk = 0; kk < 32; kk++) {
            float4 h = h4[kk];
            a0 = fmaf(wreg[kk].x, h.x, a0); a1 = fmaf(wreg[kk].y, h.y, a1);
            a2 = fmaf(wreg[kk].z, h.z, a2); a3 = fmaf(wreg[kk].w, h.w, a3);
        }
        g_xpre2[s * G4 + n] = bias + ((a0 + a1) + (a2 + a3));
    }
}

// ---------------- MLP head: fuse m1_w @ m2_w (no nonlinearity in head) ----------------
__global__ void k_fw(const float* __restrict__ m1w, const float* __restrict__ m2w) {
    int i = blockIdx.x;
    float s = 0.f;
    for (int j = threadIdx.x; j < 576; j += 64) s += m1w[i * 576 + j] * m2w[j];
    #pragma unroll
    for (int off = 16; off > 0; off >>= 1) s += __shfl_down_sync(0xffffffffu, s, off);
    __shared__ float sm[2];
    if ((threadIdx.x & 31) == 0) sm[threadIdx.x >> 5] = s;
    __syncthreads();
    if (threadIdx.x == 0) g_fw[i] = sm[0] + sm[1];
}

__global__ void k_final(const float* __restrict__ m1b, const float* __restrict__ m2w,
                        const float* __restrict__ m2b, float* __restrict__ out) {
    __shared__ float red[512];
    float s = 0.f;
    for (int i = threadIdx.x; i < 9 * HH; i += 512) s += g_dvec[i] * g_fw[i];
    for (int j = threadIdx.x; j < 576; j += 512) s += m1b[j] * m2w[j];
    red[threadIdx.x] = s;
    __syncthreads();
    for (int st = 256; st > 0; st >>= 1) {
        if (threadIdx.x < st) red[threadIdx.x] += red[threadIdx.x + st];
        __syncthreads();
    }
    if (threadIdx.x == 0) out[0] = red[0] + m2b[0];
}

// ---------------- launch ----------------
extern "C" void kernel_launch(void* const* d_in, const int* in_sizes, int n_in,
                              void* d_out, int out_size) {
    const float* data0 = (const float*)d_in[0];
    const float* data1 = (const float*)d_in[1];
    const int*   ei    = (const int*)d_in[2];
    const float* W1   = (const float*)d_in[3];
    const float* b1   = (const float*)d_in[4];
    const float* W2   = (const float*)d_in[5];
    const float* b2   = (const float*)d_in[6];
    const float* Wih1 = (const float*)d_in[7];
    const float* Whh1 = (const float*)d_in[8];
    const float* bih1 = (const float*)d_in[9];
    const float* bhh1 = (const float*)d_in[10];
    const float* Wih2 = (const float*)d_in[11];
    const float* Whh2 = (const float*)d_in[12];
    const float* bih2 = (const float*)d_in[13];
    const float* bhh2 = (const float*)d_in[14];
    const float* m1w  = (const float*)d_in[15];
    const float* m1b  = (const float*)d_in[16];
    const float* m2w  = (const float*)d_in[17];
    const float* m2b  = (const float*)d_in[18];
    float* out = (float*)d_out;

    static cudaStream_t s2 = nullptr;
    static cudaEvent_t evA = nullptr, evB = nullptr;
    if (!s2) {
        cudaStreamCreateWithFlags(&s2, cudaStreamNonBlocking);
        cudaEventCreateWithFlags(&evA, cudaEventDisableTiming);
        cudaEventCreateWithFlags(&evB, cudaEventDisableTiming);
    }

    // fork: GCN chain + head-weight fold run on s2, LSTM chain on default stream.
    // Host launch order puts k_lstm_cl 4th so ncu's fixed capture slot profiles it.
    cudaEventRecord(evA, 0);
    cudaStreamWaitEvent(s2, evA, 0);

    k_xpre<<<dim3(100, 8), 256>>>(data0, Wih1, bih1, bhh1);          // launch 1 (default)
    k_zero<<<(MAXSLOTS * HH + 255) / 256, 256, 0, s2>>>();           // launch 2 (s2)
    k_scan1<<<(EE + 255) / 256, 256, 0, s2>>>(ei);                   // launch 3 (s2)
    k_lstm_cl<<<2 * BB, 256>>>(Whh1, TT, 1);                         // launch 4 (default) <- ncu slot
    k_dedupe<<<1, MAXT, 0, s2>>>();                                  // launch 5 (s2)
    k_scan2<<<(EE + 255) / 256, 256, 0, s2>>>(ei);                   // launch 6 (s2)
    k_l1agg<<<256, HH, 0, s2>>>(data1);
    k_l1mat<<<128, HH, 0, s2>>>(data1, W1, b1);
    k_l2agg<<<64, HH, 0, s2>>>();
    k_l2mat<<<8, HH, 0, s2>>>(W2, b2);
    k_fw<<<1152, 64, 0, s2>>>(m1w, m2w);

    k_xpre2<<<4, 128>>>(Wih2, bih2, bhh2);
    k_lstm_cl<<<2, 256>>>(Whh2, BB, 2);

    // join
    cudaEventRecord(evB, s2);
    cudaStreamWaitEvent(0, evB, 0);
    k_final<<<1, 512>>>(m1b, m2w, m2b, out);
}